// round 7
// baseline (speedup 1.0000x reference)
#include <cuda_runtime.h>
#include <cstdint>

// VectorQuantizer: z [N=262144 rows, D=64], emb [K=1024, D=64]
// out = [ z_q_st (N*D floats) , vq_loss , perplexity ]
//
// Bit-exactness vs reference (jax fp32):
//   znorm  = NEON-W4 reduce: p_l = seq sum fl(z*z)[4k+l]; (p0+p2)+(p1+p3)
//   dot    = sequential-d fp32 FMA
//   score  = fl( fl(znorm - 2*dot) + enorm )
//   argmin = first-index tie-break
//   out    = fl( z + fl(z_q - z) )

#define D       64
#define K       1024
#define BM      128          // rows per block
#define BK      128          // codes per tile
#define NTILES  (K / BK)     // 8
#define THREADS 256

#define ZS_STRIDE 65         // u64 units  (row-pairs 0..63 + pad)
#define ES_STRIDE 65         // f32 units  (d 0..63 + pad), code-major [c][d]
// zs2 u64[64][65]=33280 + esf f32[128][65]=33280 + cs 512 + idxs 512 + znrm 512
#define SMEM_BYTES (D*ZS_STRIDE*8 + BK*ES_STRIDE*4 + BK*4 + BM*4 + BM*4)

__device__ float        g_C[K];        // enorm_k
__device__ int          g_counts[K];
__device__ double       g_loss;
__device__ unsigned int g_done;

__device__ __forceinline__ void ffma2(unsigned long long& d,
                                      unsigned long long a,
                                      unsigned long long b) {
    asm("fma.rn.f32x2 %0, %1, %2, %0;" : "+l"(d) : "l"(a), "l"(b));
}

__device__ __forceinline__ unsigned long long dup2f(float x) {
    unsigned long long r;
    unsigned int u = __float_as_uint(x);
    asm("mov.b64 %0, {%1, %1};" : "=l"(r) : "r"(u));
    return r;
}

__device__ __forceinline__ float lo32(unsigned long long v) {
    return __uint_as_float((unsigned int)(v & 0xffffffffull));
}
__device__ __forceinline__ float hi32(unsigned long long v) {
    return __uint_as_float((unsigned int)(v >> 32));
}

// ---------------------------------------------------------------------------
// init: enorm_k = XLA-order sum of rounded squares; zero hist/loss/counter
// ---------------------------------------------------------------------------
__global__ void vq_init(const float* __restrict__ emb) {
    int k = blockIdx.x * blockDim.x + threadIdx.x;
    if (k < K) {
        const float* e = emb + (size_t)k * D;
        float p[4] = {0.f, 0.f, 0.f, 0.f};
        #pragma unroll
        for (int c = 0; c < 16; ++c) {
            #pragma unroll
            for (int l = 0; l < 4; ++l) {
                float sq = __fmul_rn(e[4 * c + l], e[4 * c + l]);
                p[l] = __fadd_rn(p[l], sq);
            }
        }
        g_C[k] = __fadd_rn(__fadd_rn(p[0], p[2]), __fadd_rn(p[1], p[3]));
        g_counts[k] = 0;
    }
    if (k == 0) { g_loss = 0.0; g_done = 0u; }
}

// ---------------------------------------------------------------------------
// main: distance-GEMM + argmin + gather + loss/hist; last CTA finalizes
// ---------------------------------------------------------------------------
__global__ __launch_bounds__(THREADS, 2) void vq_main(
    const float* __restrict__ z, const float* __restrict__ emb,
    float* __restrict__ out, long long zn, int nrows, int write_scalars)
{
    extern __shared__ unsigned char smem_raw[];
    unsigned long long* zs2 = (unsigned long long*)smem_raw;          // [64][65] u64
    float* esf  = (float*)(zs2 + D * ZS_STRIDE);                      // [128][65] f32 (code-major)
    float* cs   = esf + BK * ES_STRIDE;                               // [128]
    int*   idxs = (int*)(cs + BK);                                    // [128]
    float* znrm = (float*)(idxs + BM);                                // [128]

    const int tid = threadIdx.x;
    const int rpg = tid >> 4;   // 0..15 : base row-pair group
    const int cg  = tid & 15;   // 0..15 : code lane (codes strided by 16)
    const long long R0 = (long long)blockIdx.x * BM;

    // ---- load z tile -> SMEM, row-pair packed, d-major ----
    {
        const float4* zg = (const float4*)(z + R0 * D);
        unsigned int* zsw = (unsigned int*)zs2;
        #pragma unroll
        for (int t = 0; t < 8; ++t) {
            int f   = tid + t * THREADS;          // 0..2047, coalesced gmem
            int row = f >> 4;
            int d0  = (f & 15) << 2;
            float4 v = zg[f];
            int rp = row >> 1, par = row & 1;
            zsw[((d0 + 0) * ZS_STRIDE + rp) * 2 + par] = __float_as_uint(v.x);
            zsw[((d0 + 1) * ZS_STRIDE + rp) * 2 + par] = __float_as_uint(v.y);
            zsw[((d0 + 2) * ZS_STRIDE + rp) * 2 + par] = __float_as_uint(v.z);
            zsw[((d0 + 3) * ZS_STRIDE + rp) * 2 + par] = __float_as_uint(v.w);
        }
    }
    __syncthreads();

    // ---- znorm per row (threads 0..127), XLA NEON-W4 order ----
    if (tid < BM) {
        const unsigned int* zsw = (const unsigned int*)zs2;
        int row = tid, rp = row >> 1, par = row & 1;
        float p[4] = {0.f, 0.f, 0.f, 0.f};
        #pragma unroll
        for (int c = 0; c < 16; ++c) {
            #pragma unroll
            for (int l = 0; l < 4; ++l) {
                int d = 4 * c + l;
                float zv = __uint_as_float(zsw[(d * ZS_STRIDE + rp) * 2 + par]);
                p[l] = __fadd_rn(p[l], __fmul_rn(zv, zv));
            }
        }
        znrm[row] = __fadd_rn(__fadd_rn(p[0], p[2]), __fadd_rn(p[1], p[3]));
    }
    __syncthreads();

    float zn8[8];
    #pragma unroll
    for (int i = 0; i < 4; ++i) {
        zn8[2 * i]     = znrm[2 * (rpg + 16 * i)];
        zn8[2 * i + 1] = znrm[2 * (rpg + 16 * i) + 1];
    }

    float bst[8];
    int   bix[8];
    #pragma unroll
    for (int i = 0; i < 8; ++i) { bst[i] = 3.4e38f; bix[i] = 0; }

    for (int t = 0; t < NTILES; ++t) {
        __syncthreads();   // protect esf reuse

        // ---- load e tile (128 codes x 64 dims) -> f32, code-major [c][d] ----
        {
            const float4* eg = (const float4*)(emb + (size_t)t * BK * D);
            #pragma unroll
            for (int q = 0; q < 8; ++q) {
                int f  = tid + q * THREADS;       // 0..2047, coalesced gmem
                int c  = f >> 4;                  // 0..127
                int d0 = (f & 15) << 2;
                float4 v = eg[f];
                float* ep = esf + c * ES_STRIDE + d0;
                ep[0] = v.x; ep[1] = v.y; ep[2] = v.z; ep[3] = v.w;
            }
            if (tid < BK) cs[tid] = g_C[t * BK + tid];
        }
        __syncthreads();

        // ---- compute: 4 row-pairs x 8 codes, sequential-d FMA ----
        unsigned long long acc[4][8];
        #pragma unroll
        for (int i = 0; i < 4; ++i)
            #pragma unroll
            for (int j = 0; j < 8; ++j) acc[i][j] = 0ull;

        const unsigned long long* zb = zs2 + rpg;
        const float* eb = esf + cg * ES_STRIDE;   // + j*16*ES_STRIDE + d
        #pragma unroll 4
        for (int d = 0; d < D; ++d) {
            unsigned long long a0 = zb[d * ZS_STRIDE];
            unsigned long long a1 = zb[d * ZS_STRIDE + 16];
            unsigned long long a2 = zb[d * ZS_STRIDE + 32];
            unsigned long long a3 = zb[d * ZS_STRIDE + 48];
            #pragma unroll
            for (int j = 0; j < 8; ++j) {
                unsigned long long b = dup2f(eb[j * 16 * ES_STRIDE + d]);
                ffma2(acc[0][j], a0, b);
                ffma2(acc[1][j], a1, b);
                ffma2(acc[2][j], a2, b);
                ffma2(acc[3][j], a3, b);
            }
        }

        // ---- epilogue: s = fl(fl(znorm - 2*dot) + enorm), running argmin ----
        #pragma unroll
        for (int i = 0; i < 4; ++i) {
            #pragma unroll
            for (int j = 0; j < 8; ++j) {
                int code = t * BK + cg + 16 * j;   // ascending per thread
                float c2 = cs[cg + 16 * j];
                float t0 = __fsub_rn(zn8[2 * i],     2.0f * lo32(acc[i][j]));
                float t1 = __fsub_rn(zn8[2 * i + 1], 2.0f * hi32(acc[i][j]));
                float s0 = __fadd_rn(t0, c2);
                float s1 = __fadd_rn(t1, c2);
                if (s0 < bst[2 * i])     { bst[2 * i]     = s0; bix[2 * i]     = code; }
                if (s1 < bst[2 * i + 1]) { bst[2 * i + 1] = s1; bix[2 * i + 1] = code; }
            }
        }
    }

    // ---- cross-lane argmin per row (16 lanes/half-warp share rows) ----
    #pragma unroll
    for (int m = 1; m < 16; m <<= 1) {
        #pragma unroll
        for (int s = 0; s < 8; ++s) {
            float os = __shfl_xor_sync(0xffffffffu, bst[s], m);
            int   oi = __shfl_xor_sync(0xffffffffu, bix[s], m);
            if (os < bst[s] || (os == bst[s] && oi < bix[s])) {
                bst[s] = os; bix[s] = oi;
            }
        }
    }
    if (cg == 0) {
        #pragma unroll
        for (int i = 0; i < 4; ++i) {
            idxs[2 * (rpg + 16 * i)]     = bix[2 * i];
            idxs[2 * (rpg + 16 * i) + 1] = bix[2 * i + 1];
        }
    }
    __syncthreads();

    // ---- gather z_q rows, emulate ST output, commitment-loss partial ----
    float lsum = 0.f;
    const unsigned int* zsw = (const unsigned int*)zs2;
    #pragma unroll
    for (int r0 = 0; r0 < BM; r0 += 64) {
        int row  = r0 + (tid >> 2);
        int part = tid & 3;
        int idx  = idxs[row];
        const float4* ep = (const float4*)(emb + (size_t)idx * D);
        float4*       op = (float4*)(out + (R0 + row) * D);
        int rp = row >> 1, par = row & 1;
        #pragma unroll
        for (int j = 0; j < 4; ++j) {
            int d0 = part * 16 + j * 4;
            float4 e4 = ep[d0 >> 2];
            float z0 = __uint_as_float(zsw[((d0 + 0) * ZS_STRIDE + rp) * 2 + par]);
            float z1 = __uint_as_float(zsw[((d0 + 1) * ZS_STRIDE + rp) * 2 + par]);
            float z2 = __uint_as_float(zsw[((d0 + 2) * ZS_STRIDE + rp) * 2 + par]);
            float z3 = __uint_as_float(zsw[((d0 + 3) * ZS_STRIDE + rp) * 2 + par]);
            float d0f = __fsub_rn(e4.x, z0);
            float d1f = __fsub_rn(e4.y, z1);
            float d2f = __fsub_rn(e4.z, z2);
            float d3f = __fsub_rn(e4.w, z3);
            float4 q;
            q.x = __fadd_rn(z0, d0f);
            q.y = __fadd_rn(z1, d1f);
            q.z = __fadd_rn(z2, d2f);
            q.w = __fadd_rn(z3, d3f);
            op[d0 >> 2] = q;
            lsum = fmaf(d0f, d0f, lsum);
            lsum = fmaf(d1f, d1f, lsum);
            lsum = fmaf(d2f, d2f, lsum);
            lsum = fmaf(d3f, d3f, lsum);
        }
    }

    // ---- block-reduce loss, global atomics ----
    #pragma unroll
    for (int o = 16; o; o >>= 1) lsum += __shfl_xor_sync(0xffffffffu, lsum, o);
    __shared__ float wsum[8];
    if ((tid & 31) == 0) wsum[tid >> 5] = lsum;
    __syncthreads();
    if (tid == 0) {
        float s = 0.f;
        #pragma unroll
        for (int w = 0; w < 8; ++w) s += wsum[w];
        atomicAdd(&g_loss, (double)s);
    }
    if (tid < BM) atomicAdd(&g_counts[idxs[tid]], 1);

    // ---- last CTA: finalize scalars ----
    __shared__ unsigned int s_last;
    __syncthreads();
    if (tid == 0) {
        __threadfence();
        unsigned int v = atomicAdd(&g_done, 1u);
        s_last = (v == gridDim.x - 1) ? 1u : 0u;
    }
    __syncthreads();
    if (s_last && write_scalars) {
        __threadfence();
        double term = 0.0;
        #pragma unroll
        for (int m = 0; m < 4; ++m) {
            int k = tid * 4 + m;
            double p = (double)g_counts[k] / (double)nrows;
            term += p * log(p + 1e-5);
        }
        #pragma unroll
        for (int o = 16; o; o >>= 1) term += __shfl_xor_sync(0xffffffffu, term, o);
        __shared__ double dsum[8];
        if ((tid & 31) == 0) dsum[tid >> 5] = term;
        __syncthreads();
        if (tid == 0) {
            double v = 0.0;
            #pragma unroll
            for (int w = 0; w < 8; ++w) v += dsum[w];
            out[zn]     = (float)(0.25 * (g_loss / (double)zn));  // vq_loss
            out[zn + 1] = (float)exp(-v);                         // perplexity
        }
    }
}

// ---------------------------------------------------------------------------
extern "C" void kernel_launch(void* const* d_in, const int* in_sizes, int n_in,
                              void* d_out, int out_size) {
    int zi = 0, ei = 1;
    if (n_in >= 2 && in_sizes[1] > in_sizes[0]) { zi = 1; ei = 0; }
    const float* z   = (const float*)d_in[zi];
    const float* emb = (const float*)d_in[ei];
    float* out = (float*)d_out;

    long long zn = (long long)in_sizes[zi];
    int nrows   = (int)(zn / D);
    int nblocks = nrows / BM;
    int write_scalars = ((long long)out_size >= zn + 2) ? 1 : 0;

    cudaFuncSetAttribute(vq_main, cudaFuncAttributeMaxDynamicSharedMemorySize,
                         SMEM_BYTES);

    vq_init<<<(K + 127) / 128, 128>>>(emb);
    vq_main<<<nblocks, THREADS, SMEM_BYTES>>>(z, emb, out, zn, nrows,
                                              write_scalars);
}